// round 13
// baseline (speedup 1.0000x reference)
#include <cuda_runtime.h>
#include <cuda_bf16.h>
#include <cstdint>

// ---------------- problem constants ----------------
#define B 32
#define NOISE 128
#define H 512
#define O 1024
#define HEADS 8
#define T 128
#define S 1024          // 2*H
#define G3 1536         // 3*H
#define NW 8192         // O*HEADS
#define NROWS 4096      // B*T
#define EOS 1023
#define SLOPE 0.2f
#define EPS_BN 1e-5f
#define EPS_COS 1e-8f

#define NBLK 64
#define BLKT 512
#define LDS_XB 80               // loop: x staged bf16 rows, 80B padded
#define SMEM_DYN (2 * H * LDS_XB)     // 81920 B (k_loop)

// ---------------- device scratch (static, no allocs) ----------------
__device__ __align__(16) float g_hT[H * B];
__device__ __align__(16) float g_mT[H * B];
__device__ __align__(16) float g_zpartT[H * B];
__device__ __align__(16) float g_pebnT[H * B];
__device__ __align__(16) float g_gizT[G3 * B];
__device__ __align__(16) float g_gihT[G3 * B];
__device__ __align__(16) float g_ghhT[G3 * B];
__device__ __align__(16) float g_ghmT[G3 * B];
__device__ __align__(16) float g_gimem[T * G3];
__device__ __align__(16) float g_xhT[H * B];
__device__ __align__(16) float g_xmT[H * B];
__device__ __align__(16) float g_logitsR[64 * O];
__device__ int g_prev[B];
// b-major: row = b*T + t  (same as R10)
__device__ __align__(16) float g_outs[NROWS * O];
__device__ __align__(16) float g_mems[NROWS * O];

// bf16 hi/lo splits
__device__ __align__(16) __nv_bfloat16 g_A0hi[NROWS * O];
__device__ __align__(16) __nv_bfloat16 g_A0lo[NROWS * O];
__device__ __align__(16) __nv_bfloat16 g_A1hi[NROWS * O];
__device__ __align__(16) __nv_bfloat16 g_A1lo[NROWS * O];
__device__ __align__(16) __nv_bfloat16 g_Whi[(size_t)NW * O];
__device__ __align__(16) __nv_bfloat16 g_Wlo[(size_t)NW * O];
__device__ __align__(16) __nv_bfloat16 g_WhhHi[G3 * H];
__device__ __align__(16) __nv_bfloat16 g_WhhLo[G3 * H];
__device__ __align__(16) __nv_bfloat16 g_WihHi[G3 * S];
__device__ __align__(16) __nv_bfloat16 g_WihLo[G3 * S];
__device__ __align__(16) __nv_bfloat16 g_WoHi[O * H];
__device__ __align__(16) __nv_bfloat16 g_WoLo[O * H];

// grid barrier state (replay-safe)
__device__ unsigned g_barcnt = 0;
__device__ unsigned g_bargen = 0;

// ---------------- helpers ----------------
__device__ __forceinline__ float wsum(float v) {
#pragma unroll
    for (int o = 16; o > 0; o >>= 1) v += __shfl_xor_sync(0xffffffffu, v, o);
    return v;
}
__device__ __forceinline__ float lrelu(float x) { return x >= 0.f ? x : SLOPE * x; }
__device__ __forceinline__ float sigm(float x) { return 1.f / (1.f + expf(-x)); }

__device__ __forceinline__ void grid_barrier() {
    __syncthreads();
    __threadfence();
    if (threadIdx.x == 0) {
        unsigned gen = *(volatile unsigned*)&g_bargen;
        unsigned arr = atomicAdd(&g_barcnt, 1u);
        if (arr == NBLK - 1) {
            atomicExch(&g_barcnt, 0u);
            __threadfence();
            atomicExch(&g_bargen, gen + 1u);
        } else {
            while (*(volatile unsigned*)&g_bargen == gen) __nanosleep(32);
        }
    }
    __syncthreads();
}

extern __shared__ float sAct[];

__device__ __forceinline__ void stage_x(const float* __restrict__ src) {
    __nv_bfloat162* hi = reinterpret_cast<__nv_bfloat162*>(sAct);
    __nv_bfloat162* lo = hi + H * 20;
    for (int i = threadIdx.x; i < H * 16; i += BLKT) {
        int k = i >> 4, bp = i & 15;
        float2 v = __ldcg(reinterpret_cast<const float2*>(src) + i);
        __nv_bfloat16 hx = __float2bfloat16(v.x), hy = __float2bfloat16(v.y);
        hi[k * 20 + bp] = __nv_bfloat162(hx, hy);
        lo[k * 20 + bp] = __nv_bfloat162(__float2bfloat16(v.x - __bfloat162float(hx)),
                                         __float2bfloat16(v.y - __bfloat162float(hy)));
    }
    __syncthreads();
}

// ---------------- mma helpers (legacy path) ----------------
__device__ __forceinline__ void ldsm4(uint32_t& r0, uint32_t& r1, uint32_t& r2,
                                      uint32_t& r3, uint32_t addr) {
    asm volatile("ldmatrix.sync.aligned.m8n8.x4.shared.b16 {%0,%1,%2,%3}, [%4];"
                 : "=r"(r0), "=r"(r1), "=r"(r2), "=r"(r3) : "r"(addr));
}
__device__ __forceinline__ void ldsm2t(uint32_t& r0, uint32_t& r1, uint32_t addr) {
    asm volatile("ldmatrix.sync.aligned.m8n8.x2.trans.shared.b16 {%0,%1}, [%2];"
                 : "=r"(r0), "=r"(r1) : "r"(addr));
}
__device__ __forceinline__ void mma_bf16(float* c, uint32_t a0, uint32_t a1,
                                         uint32_t a2, uint32_t a3,
                                         uint32_t b0, uint32_t b1) {
    asm volatile("mma.sync.aligned.m16n8k16.row.col.f32.bf16.bf16.f32 "
                 "{%0,%1,%2,%3}, {%4,%5,%6,%7}, {%8,%9}, {%0,%1,%2,%3};"
                 : "+f"(c[0]), "+f"(c[1]), "+f"(c[2]), "+f"(c[3])
                 : "r"(a0), "r"(a1), "r"(a2), "r"(a3), "r"(b0), "r"(b1));
}
__device__ __forceinline__ void cp16(uint32_t smem_dst, const void* gsrc) {
    asm volatile("cp.async.ca.shared.global [%0], [%1], 16;"
                 :: "r"(smem_dst), "l"(gsrc));
}

// loop warp task: D[m16 x n32] += (Whi+Wlo)·(xhi+xlo), K=512, 3-pass.
__device__ __forceinline__ void gemm_tile(
    float d[4][4],
    const __nv_bfloat16* __restrict__ Whi, const __nv_bfloat16* __restrict__ Wlo,
    int ldk, int m0, uint32_t xhi_b, uint32_t xlo_b, int lane)
{
    const int g = lane >> 2, tig = lane & 3;
    const __nv_bfloat16* w0h = Whi + (size_t)(m0 + g) * ldk + 2 * tig;
    const __nv_bfloat16* w8h = Whi + (size_t)(m0 + g + 8) * ldk + 2 * tig;
    const __nv_bfloat16* w0l = Wlo + (size_t)(m0 + g) * ldk + 2 * tig;
    const __nv_bfloat16* w8l = Wlo + (size_t)(m0 + g + 8) * ldk + 2 * tig;
    const uint32_t xrow = (uint32_t)(lane & 15);
#pragma unroll 4
    for (int k0 = 0; k0 < H; k0 += 16) {
        uint32_t ah[4], al[4];
        ah[0] = *reinterpret_cast<const uint32_t*>(w0h + k0);
        ah[1] = *reinterpret_cast<const uint32_t*>(w8h + k0);
        ah[2] = *reinterpret_cast<const uint32_t*>(w0h + k0 + 8);
        ah[3] = *reinterpret_cast<const uint32_t*>(w8h + k0 + 8);
        al[0] = *reinterpret_cast<const uint32_t*>(w0l + k0);
        al[1] = *reinterpret_cast<const uint32_t*>(w8l + k0);
        al[2] = *reinterpret_cast<const uint32_t*>(w0l + k0 + 8);
        al[3] = *reinterpret_cast<const uint32_t*>(w8l + k0 + 8);
        uint32_t rb = (uint32_t)(k0 + xrow) * LDS_XB;
#pragma unroll
        for (int nt = 0; nt < 4; nt++) {
            uint32_t bh0, bh1, bl0, bl1;
            ldsm2t(bh0, bh1, xhi_b + rb + nt * 16);
            ldsm2t(bl0, bl1, xlo_b + rb + nt * 16);
            mma_bf16(d[nt], ah[0], ah[1], ah[2], ah[3], bh0, bh1);
            mma_bf16(d[nt], al[0], al[1], al[2], al[3], bh0, bh1);
            mma_bf16(d[nt], ah[0], ah[1], ah[2], ah[3], bl0, bl1);
        }
    }
}

// ---------------- init ----------------
__global__ void k_init(const float* __restrict__ z, const float* __restrict__ w,
                       const float* __restrict__ wb,
                       const float* __restrict__ g1, const float* __restrict__ b1,
                       const float* __restrict__ g2, const float* __restrict__ b2) {
    int j = blockIdx.x;
    int b = threadIdx.x;
    const float* wr = w + (size_t)j * NOISE;
    const float* zr = z + (size_t)b * NOISE;
    float acc = wb[j];
#pragma unroll 8
    for (int k = 0; k < NOISE; k++) acc += zr[k] * wr[k];
    float v = lrelu(acc);
    float mu = wsum(v) * (1.f / B);
    float m2 = wsum(v * v) * (1.f / B);
    float var = fmaxf(m2 - mu * mu, 0.f);
    float z0 = (v - mu) * rsqrtf(var + EPS_BN) * g1[j] + b1[j];
    float mu2 = wsum(z0) * (1.f / B);
    float q2 = wsum(z0 * z0) * (1.f / B);
    float var2 = fmaxf(q2 - mu2 * mu2, 0.f);
    float zp = (z0 - mu2) * rsqrtf(var2 + EPS_BN) * g2[H + j] + b2[H + j];
    g_hT[j * B + b] = z0;
    g_mT[j * B + b] = z0;
    g_zpartT[j * B + b] = zp;
    if (j == 0) g_prev[b] = EOS;
}

// ---------------- gi_z (once) ----------------
__global__ void k_giz(const float* __restrict__ w_ih, const float* __restrict__ b_ih) {
    int c = blockIdx.x;
    int b = threadIdx.x;
    const float* wr = w_ih + (size_t)c * S + H;
    float a0 = b_ih[c], a1 = 0.f, a2 = 0.f, a3 = 0.f;
#pragma unroll 16
    for (int k = 0; k < H; k += 4) {
        float4 wv = *reinterpret_cast<const float4*>(wr + k);
        a0 += g_zpartT[(k + 0) * B + b] * wv.x;
        a1 += g_zpartT[(k + 1) * B + b] * wv.y;
        a2 += g_zpartT[(k + 2) * B + b] * wv.z;
        a3 += g_zpartT[(k + 3) * B + b] * wv.w;
    }
    g_gizT[c * B + b] = (a0 + a1) + (a2 + a3);
}

// ---------------- gi_mem (once) ----------------
__global__ void k_gimem(const float* __restrict__ memory, const int* __restrict__ perm,
                        const float* __restrict__ w_ih, const float* __restrict__ b_ih) {
    __shared__ __align__(16) float xs[S];
    int t = blockIdx.y;
    int p = perm[t];
    for (int i = threadIdx.x; i < S; i += blockDim.x) xs[i] = memory[(size_t)p * S + i];
    __syncthreads();
    int ws = threadIdx.x >> 5, lane = threadIdx.x & 31;
    int c = blockIdx.x * 16 + ws;
    const float* wr = w_ih + (size_t)c * S;
    float partial = 0.f;
#pragma unroll 8
    for (int k = lane; k < S; k += 32) partial += xs[k] * wr[k];
    partial = wsum(partial);
    if (lane == 0) g_gimem[t * G3 + c] = partial + b_ih[c];
}

// ---------------- bf16 hi/lo split ----------------
// which: 0 outs->A0, 1 mems->A1, 2 lin_w->W, 3 w_hh->Whh, 4 w_ih->Wih, 5 h2o->Wo
__global__ void k_split(const float* __restrict__ src_ext, int which, int n4) {
    int i = blockIdx.x * blockDim.x + threadIdx.x;
    if (i >= n4) return;
    const float* src;
    __nv_bfloat16* hi;
    __nv_bfloat16* lo;
    if (which == 0)      { src = g_outs; hi = g_A0hi; lo = g_A0lo; }
    else if (which == 1) { src = g_mems; hi = g_A1hi; lo = g_A1lo; }
    else if (which == 2) { src = src_ext; hi = g_Whi;   lo = g_Wlo; }
    else if (which == 3) { src = src_ext; hi = g_WhhHi; lo = g_WhhLo; }
    else if (which == 4) { src = src_ext; hi = g_WihHi; lo = g_WihLo; }
    else                 { src = src_ext; hi = g_WoHi;  lo = g_WoLo; }
    float4 v = __ldcg(reinterpret_cast<const float4*>(src) + i);
    __nv_bfloat16 hx = __float2bfloat16(v.x), hy = __float2bfloat16(v.y);
    __nv_bfloat16 hz = __float2bfloat16(v.z), hw = __float2bfloat16(v.w);
    __nv_bfloat162* hp = reinterpret_cast<__nv_bfloat162*>(hi) + i * 2;
    hp[0] = __nv_bfloat162(hx, hy); hp[1] = __nv_bfloat162(hz, hw);
    __nv_bfloat162* lp = reinterpret_cast<__nv_bfloat162*>(lo) + i * 2;
    lp[0] = __nv_bfloat162(__float2bfloat16(v.x - __bfloat162float(hx)),
                           __float2bfloat16(v.y - __bfloat162float(hy)));
    lp[1] = __nv_bfloat162(__float2bfloat16(v.z - __bfloat162float(hz)),
                           __float2bfloat16(v.w - __bfloat162float(hw)));
}

// ---------------- persistent recurrent loop (verbatim R10) ----------------
__global__ void __launch_bounds__(BLKT)
k_loop(const float* __restrict__ emb, const float* __restrict__ g2,
       const float* __restrict__ b2,
       const float* __restrict__ b_hh,
       const float* __restrict__ g3, const float* __restrict__ b3,
       const float* __restrict__ h2o_b) {
    const int tid = threadIdx.x;
    const int lane = tid & 31;
    const int wib = tid >> 5;
    const int wid = (blockIdx.x * BLKT + tid) >> 5;
    const bool path1 = (blockIdx.x >= 32);
    const uint32_t xhi_b = (uint32_t)__cvta_generic_to_shared(sAct);
    const uint32_t xlo_b = xhi_b + H * LDS_XB;
    const int g = lane >> 2, tig = lane & 3;

    for (int t = 0; t < T; t++) {
        // Phase A: gh GEMM (warps 0-2) + pe bn2 (warps 3-10)
        stage_x(path1 ? g_mT : g_hT);
        if (wib < 3) {
            int m0 = ((blockIdx.x & 31) * 3 + wib) * 16;
            float d[4][4];
#pragma unroll
            for (int i = 0; i < 4; i++)
#pragma unroll
                for (int q = 0; q < 4; q++) d[i][q] = 0.f;
            gemm_tile(d, g_WhhHi, g_WhhLo, H, m0, xhi_b, xlo_b, lane);
            float* out = path1 ? g_ghmT : g_ghhT;
            int c0 = m0 + g, c8 = c0 + 8;
            float bz0 = b_hh[c0], bz8 = b_hh[c8];
#pragma unroll
            for (int nt = 0; nt < 4; nt++) {
                int b0 = nt * 8 + 2 * tig;
                __stcg(reinterpret_cast<float2*>(&out[c0 * B + b0]),
                       make_float2(d[nt][0] + bz0, d[nt][1] + bz0));
                __stcg(reinterpret_cast<float2*>(&out[c8 * B + b0]),
                       make_float2(d[nt][2] + bz8, d[nt][3] + bz8));
            }
        } else if (wib < 11) {
            int j = blockIdx.x * 8 + (wib - 3);
            int idx = __ldcg(&g_prev[lane]);
            float v = lrelu(emb[(size_t)idx * H + j]);
            float mu = wsum(v) * (1.f / B);
            float m2 = wsum(v * v) * (1.f / B);
            float var = fmaxf(m2 - mu * mu, 0.f);
            __stcg(&g_pebnT[j * B + lane],
                   (v - mu) * rsqrtf(var + EPS_BN) * g2[j] + b2[j]);
        }
        grid_barrier();

        // Phase B: gi_h
        stage_x(g_pebnT);
        {
            int tk = -1;
            if (blockIdx.x < 32) { if (wib < 2) tk = blockIdx.x * 2 + wib; }
            else                 { if (wib == 0) tk = 64 + (blockIdx.x - 32); }
            if (tk >= 0) {
                int m0 = tk * 16;
                float d[4][4];
#pragma unroll
                for (int i = 0; i < 4; i++)
#pragma unroll
                    for (int q = 0; q < 4; q++) d[i][q] = 0.f;
                gemm_tile(d, g_WihHi, g_WihLo, S, m0, xhi_b, xlo_b, lane);
                int c0 = m0 + g, c8 = c0 + 8;
#pragma unroll
                for (int nt = 0; nt < 4; nt++) {
                    int b0 = nt * 8 + 2 * tig;
                    float2 z0 = __ldcg(reinterpret_cast<const float2*>(&g_gizT[c0 * B + b0]));
                    float2 z8 = __ldcg(reinterpret_cast<const float2*>(&g_gizT[c8 * B + b0]));
                    __stcg(reinterpret_cast<float2*>(&g_gihT[c0 * B + b0]),
                           make_float2(d[nt][0] + z0.x, d[nt][1] + z0.y));
                    __stcg(reinterpret_cast<float2*>(&g_gihT[c8 * B + b0]),
                           make_float2(d[nt][2] + z8.x, d[nt][3] + z8.y));
                }
            }
        }
        grid_barrier();

        // Phase C: GRU + bn3
        {
            int j = wid & 511;
            bool p1 = (wid >= 512);
            float gr, gz, gn, hr, hz, hn, hprev;
            if (!p1) {
                gr = __ldcg(&g_gihT[j * B + lane]);
                gz = __ldcg(&g_gihT[(H + j) * B + lane]);
                gn = __ldcg(&g_gihT[(2 * H + j) * B + lane]);
                hr = __ldcg(&g_ghhT[j * B + lane]);
                hz = __ldcg(&g_ghhT[(H + j) * B + lane]);
                hn = __ldcg(&g_ghhT[(2 * H + j) * B + lane]);
                hprev = __ldcg(&g_hT[j * B + lane]);
            } else {
                const float* gm = g_gimem + t * G3;
                gr = gm[j]; gz = gm[H + j]; gn = gm[2 * H + j];
                hr = __ldcg(&g_ghmT[j * B + lane]);
                hz = __ldcg(&g_ghmT[(H + j) * B + lane]);
                hn = __ldcg(&g_ghmT[(2 * H + j) * B + lane]);
                hprev = __ldcg(&g_mT[j * B + lane]);
            }
            float r = sigm(gr + hr);
            float zt = sigm(gz + hz);
            float n = tanhf(gn + r * hn);
            float hnew = (1.f - zt) * n + zt * hprev;
            __stcg(&(p1 ? g_mT : g_hT)[j * B + lane], hnew);
            float v = lrelu(hnew);
            float mu = wsum(v) * (1.f / B);
            float m2 = wsum(v * v) * (1.f / B);
            float var = fmaxf(m2 - mu * mu, 0.f);
            __stcg(&(p1 ? g_xmT : g_xhT)[j * B + lane],
                   (v - mu) * rsqrtf(var + EPS_BN) * g3[j] + b3[j]);
        }
        grid_barrier();

        // Phase D1: logits GEMM
        stage_x(path1 ? g_xmT : g_xhT);
        if (wib < 2) {
            int m0 = ((blockIdx.x & 31) * 2 + wib) * 16;
            float d[4][4];
#pragma unroll
            for (int i = 0; i < 4; i++)
#pragma unroll
                for (int q = 0; q < 4; q++) d[i][q] = 0.f;
            gemm_tile(d, g_WoHi, g_WoLo, H, m0, xhi_b, xlo_b, lane);
            int p32 = path1 ? 32 : 0;
            int c0 = m0 + g, c8 = c0 + 8;
            float bz0 = h2o_b[c0], bz8 = h2o_b[c8];
#pragma unroll
            for (int nt = 0; nt < 4; nt++) {
                int b0 = nt * 8 + 2 * tig;
                __stcg(&g_logitsR[(p32 + b0) * O + c0], d[nt][0] + bz0);
                __stcg(&g_logitsR[(p32 + b0 + 1) * O + c0], d[nt][1] + bz0);
                __stcg(&g_logitsR[(p32 + b0) * O + c8], d[nt][2] + bz8);
                __stcg(&g_logitsR[(p32 + b0 + 1) * O + c8], d[nt][3] + bz8);
            }
        }
        grid_barrier();

        // Phase D2: softmax + argmax + store (b-major row = b*T + t)
        {
            __shared__ float s_mx[16]; __shared__ int s_mi[16]; __shared__ float s_sm[16];
            __shared__ float sb_max; __shared__ int sb_idx; __shared__ float sb_sum;
            int row = blockIdx.x;
            int path = row >> 5;
            int b = row & 31;
            int o0 = tid * 2;
            float2 lv = __ldcg(reinterpret_cast<const float2*>(&g_logitsR[row * O + o0]));
            float mx = lv.x; int mi = o0;
            if (lv.y > mx) { mx = lv.y; mi = o0 + 1; }
#pragma unroll
            for (int off = 16; off > 0; off >>= 1) {
                float ov = __shfl_xor_sync(0xffffffffu, mx, off);
                int oi = __shfl_xor_sync(0xffffffffu, mi, off);
                if (ov > mx || (ov == mx && oi < mi)) { mx = ov; mi = oi; }
            }
            if (lane == 0) { s_mx[wib] = mx; s_mi[wib] = mi; }
            __syncthreads();
            if (tid == 0) {
                float bm = s_mx[0]; int bi = s_mi[0];
#pragma unroll
                for (int i = 1; i < 16; i++)
                    if (s_mx[i] > bm || (s_mx[i] == bm && s_mi[i] < bi)) { bm = s_mx[i]; bi = s_mi[i]; }
                sb_max = bm; sb_idx = bi;
            }
            __syncthreads();
            float bmax = sb_max;
            float e0 = expf(lv.x - bmax), e1 = expf(lv.y - bmax);
            float es = wsum(e0 + e1);
            if (lane == 0) s_sm[wib] = es;
            __syncthreads();
            if (tid == 0) {
                float s = 0.f;
#pragma unroll
                for (int i = 0; i < 16; i++) s += s_sm[i];
                sb_sum = s;
            }
            __syncthreads();
            float inv = 1.f / sb_sum;
            float* dst = (path ? g_mems : g_outs) + (size_t)(b * T + t) * O + o0;
            *reinterpret_cast<float2*>(dst) = make_float2(e0 * inv, e1 * inv);
            if (path == 0 && tid == 0) __stcg(&g_prev[b], sb_idx);
        }
        grid_barrier();
    }
}

// ---------------- z-paired projection + fused cosine similarity ----------------
// Tile (y,x): rows y*128 (A from outs AND mems), cols x*128 of W.
// Warp tile 32x32 per z; acc[z][mt][nt][q]. W fragments shared across z.
// Epilogue computes cossim over HEADS directly to d_out. P0/P1 never stored.
#define PZ_MAT 10240                   // 128 rows x 40 bf16 x 2B
#define PZ_STAGE (6 * PZ_MAT)          // A0hi A0lo A1hi A1lo Whi Wlo
#define PZ_SMEM (2 * PZ_STAGE)         // 122880

__global__ void __launch_bounds__(512)
k_projz(const float* __restrict__ lin_b, float* __restrict__ out) {
    extern __shared__ __align__(16) char psm[];
    const uint32_t smem0 = (uint32_t)__cvta_generic_to_shared(psm);

    const int tid = threadIdx.x;
    const int lane = tid & 31;
    const int warp = tid >> 5;        // 0..15
    const int warp_m = warp >> 2;     // 0..3 -> 32 rows each
    const int warp_n = warp & 3;      // 0..3 -> 32 cols each
    const int x = blockIdx.x;         // 0..63
    const int y = blockIdx.y;         // 0..31

    const __nv_bfloat16* A0h = g_A0hi + (size_t)(y * 128) * O;
    const __nv_bfloat16* A0l = g_A0lo + (size_t)(y * 128) * O;
    const __nv_bfloat16* A1h = g_A1hi + (size_t)(y * 128) * O;
    const __nv_bfloat16* A1l = g_A1lo + (size_t)(y * 128) * O;
    const __nv_bfloat16* Wh  = g_Whi + (size_t)(x * 128) * O;
    const __nv_bfloat16* Wl  = g_Wlo + (size_t)(x * 128) * O;

    float acc[2][2][4][4];
#pragma unroll
    for (int z = 0; z < 2; z++)
#pragma unroll
        for (int i = 0; i < 2; i++)
#pragma unroll
            for (int j = 0; j < 4; j++)
#pragma unroll
                for (int q = 0; q < 4; q++) acc[z][i][j][q] = 0.f;

    auto load_stage = [&](int kc, int st) {
        uint32_t sb = smem0 + st * PZ_STAGE;
#pragma unroll
        for (int j = 0; j < 6; j++) {
            int idx = tid + j * 512;            // 0..3071
            int mat = idx >> 9;
            int local = idx & 511;
            int row = local >> 2, q = local & 3;
            const __nv_bfloat16* src =
                (mat == 0) ? A0h : (mat == 1) ? A0l : (mat == 2) ? A1h
                : (mat == 3) ? A1l : (mat == 4) ? Wh : Wl;
            cp16(sb + mat * PZ_MAT + row * 80 + q * 16,
                 src + (size_t)row * O + kc * 32 + q * 8);
        }
        asm volatile("cp.async.commit_group;" ::: "memory");
    };

    const int a_row = (lane & 7) + 8 * ((lane >> 3) & 1);
    const int a_col = 8 * (lane >> 4);
    const int b_row = (lane & 7) + 8 * (lane >> 4);
    const int b_col = 8 * ((lane >> 3) & 1);

    load_stage(0, 0);

    for (int kc = 0; kc < 32; kc++) {
        int st = kc & 1;
        asm volatile("cp.async.wait_group 0;" ::: "memory");
        __syncthreads();
        if (kc + 1 < 32) load_stage(kc + 1, st ^ 1);

        uint32_t sb = smem0 + st * PZ_STAGE;
#pragma unroll
        for (int kk = 0; kk < 2; kk++) {
            // W fragments (shared across z)
            uint32_t bhi[4][2], blo[4][2];
#pragma unroll
            for (int nt2 = 0; nt2 < 2; nt2++) {
                int off = ((warp_n * 32 + nt2 * 16 + b_row) * 40 + kk * 16 + b_col) * 2;
                uint32_t q0, q1, q2, q3;
                ldsm4(q0, q1, q2, q3, sb + 4 * PZ_MAT + off);
                bhi[nt2 * 2][0] = q0; bhi[nt2 * 2][1] = q1;
                bhi[nt2 * 2 + 1][0] = q2; bhi[nt2 * 2 + 1][1] = q3;
                ldsm4(q0, q1, q2, q3, sb + 5 * PZ_MAT + off);
                blo[nt2 * 2][0] = q0; blo[nt2 * 2][1] = q1;
                blo[nt2 * 2 + 1][0] = q2; blo[nt2 * 2 + 1][1] = q3;
            }
#pragma unroll
            for (int z = 0; z < 2; z++) {
                uint32_t bh = sb + (z ? 2 : 0) * PZ_MAT;
                uint32_t bl = bh + PZ_MAT;
                uint32_t ahi[2][4], alo[2][4];
#pragma unroll
                for (int mt = 0; mt < 2; mt++) {
                    int off = ((warp_m * 32 + mt * 16 + a_row) * 40 + kk * 16 + a_col) * 2;
                    ldsm4(ahi[mt][0], ahi[mt][1], ahi[mt][2], ahi[mt][3], bh + off);
                    ldsm4(alo[mt][0], alo[mt][1], alo[mt][2], alo[mt][3], bl + off);
                }
#pragma unroll
                for (int mt = 0; mt < 2; mt++)
#pragma unroll
                    for (int nt = 0; nt < 4; nt++) {
                        mma_bf16(acc[z][mt][nt], ahi[mt][0], ahi[mt][1], ahi[mt][2], ahi[mt][3],
                                 bhi[nt][0], bhi[nt][1]);
                        mma_bf16(acc[z][mt][nt], alo[mt][0], alo[mt][1], alo[mt][2], alo[mt][3],
                                 bhi[nt][0], bhi[nt][1]);
                        mma_bf16(acc[z][mt][nt], ahi[mt][0], ahi[mt][1], ahi[mt][2], ahi[mt][3],
                                 blo[nt][0], blo[nt][1]);
                    }
            }
        }
        __syncthreads();
    }

    // ---- epilogue: bias + lrelu both z, cossim per head-group, direct store ----
#pragma unroll
    for (int mt = 0; mt < 2; mt++) {
#pragma unroll
        for (int q2 = 0; q2 < 2; q2++) {
            int gr = y * 128 + warp_m * 32 + mt * 16 + (lane >> 2) + q2 * 8;   // = b*T+t
            float v4[4];
#pragma unroll
            for (int nt = 0; nt < 4; nt++) {
                int col = x * 128 + warp_n * 32 + nt * 8 + 2 * (lane & 3);
                float bz0 = lin_b[col], bz1 = lin_b[col + 1];
                float a0 = lrelu(acc[0][mt][nt][2 * q2]     + bz0);
                float a1 = lrelu(acc[0][mt][nt][2 * q2 + 1] + bz1);
                float c0 = lrelu(acc[1][mt][nt][2 * q2]     + bz0);
                float c1 = lrelu(acc[1][mt][nt][2 * q2 + 1] + bz1);
                float d  = a0 * c0 + a1 * c1;
                float na = a0 * a0 + a1 * a1;
                float nb = c0 * c0 + c1 * c1;
#pragma unroll
                for (int off = 1; off <= 2; off <<= 1) {
                    d  += __shfl_xor_sync(0xffffffffu, d, off);
                    na += __shfl_xor_sync(0xffffffffu, na, off);
                    nb += __shfl_xor_sync(0xffffffffu, nb, off);
                }
                v4[nt] = d / fmaxf(sqrtf(na) * sqrtf(nb), EPS_COS);
            }
            if ((lane & 3) == 0) {
                float4 vv = make_float4(v4[0], v4[1], v4[2], v4[3]);
                *reinterpret_cast<float4*>(&out[(size_t)gr * O + x * 16 + warp_n * 4]) = vv;
            }
        }
    }
}

// ---------------- host launcher (graph-capturable, no allocs/syncs) ----------------
extern "C" void kernel_launch(void* const* d_in, const int* in_sizes, int n_in,
                              void* d_out, int out_size) {
    const float* z      = (const float*)d_in[0];
    const float* z2h_w  = (const float*)d_in[1];
    const float* z2h_b  = (const float*)d_in[2];
    const float* bn1_g  = (const float*)d_in[3];
    const float* bn1_b  = (const float*)d_in[4];
    const float* emb    = (const float*)d_in[5];
    const float* bn2_g  = (const float*)d_in[6];
    const float* bn2_b  = (const float*)d_in[7];
    const float* w_ih   = (const float*)d_in[8];
    const float* w_hh   = (const float*)d_in[9];
    const float* b_ih   = (const float*)d_in[10];
    const float* b_hh   = (const float*)d_in[11];
    const float* h2o_w  = (const float*)d_in[12];
    const float* h2o_b  = (const float*)d_in[13];
    const float* bn3_g  = (const float*)d_in[14];
    const float* bn3_b  = (const float*)d_in[15];
    const float* lin_w  = (const float*)d_in[16];
    const float* lin_b  = (const float*)d_in[17];
    const float* memory = (const float*)d_in[18];
    const int*   perm   = (const int*)d_in[19];

    cudaFuncSetAttribute(k_loop, cudaFuncAttributeMaxDynamicSharedMemorySize, SMEM_DYN);
    cudaFuncSetAttribute(k_projz, cudaFuncAttributeMaxDynamicSharedMemorySize, PZ_SMEM);

    k_init<<<H, B>>>(z, z2h_w, z2h_b, bn1_g, bn1_b, bn2_g, bn2_b);
    k_giz<<<G3, B>>>(w_ih, b_ih);
    k_gimem<<<dim3(96, T), 512>>>(memory, perm, w_ih, b_ih);

    // weight splits (before the loop)
    k_split<<<(NW * O / 4 + 255) / 256, 256>>>(lin_w, 2, NW * O / 4);
    k_split<<<(G3 * H / 4 + 255) / 256, 256>>>(w_hh, 3, G3 * H / 4);
    k_split<<<(G3 * S / 4 + 255) / 256, 256>>>(w_ih, 4, G3 * S / 4);
    k_split<<<(O * H / 4 + 255) / 256, 256>>>(h2o_w, 5, O * H / 4);

    k_loop<<<NBLK, BLKT, SMEM_DYN>>>(emb, bn2_g, bn2_b, b_hh, bn3_g, bn3_b, h2o_b);

    // activation splits
    k_split<<<(NROWS * O / 4 + 255) / 256, 256>>>(nullptr, 0, NROWS * O / 4);
    k_split<<<(NROWS * O / 4 + 255) / 256, 256>>>(nullptr, 1, NROWS * O / 4);

    k_projz<<<dim3(NW / 128, NROWS / 128), 512, PZ_SMEM>>>(lin_b, (float*)d_out);
}